// round 11
// baseline (speedup 1.0000x reference)
#include <cuda_runtime.h>
#include <cuda_bf16.h>
#include <math.h>

typedef unsigned long long ull;

// ---------------------------------------------------------------------------
// Problem constants
// ---------------------------------------------------------------------------
#define BATCH     1024
#define X_COLS    8751
#define N_IMG     8748          // 3*54*54
#define IMG_HW    54
#define IMG_RS    56            // padded image row stride (floats, 16B aligned)
#define IMG_PL    (IMG_HW * IMG_RS)     // 3024 per channel

#define P1        26
#define H1_RS     28            // padded H1 row stride
#define H1_PL     (P1 * H1_RS)          // 728 per channel
#define H1_PAD    (32 * H1_PL)          // 23296 floats

#define P2        12
#define H2_PER    (64 * P2 * P2)        // 9216

#define FCN_IN    9219
#define NTHREADS  384

// dynamic smem (floats):
//   [0, 23296)            sH1 padded [32][26][28]
//   [23296, 41728)        region2: phase1 = padded image [3][54][56] (9072);
//                         then conv2 weights as ull2[16 grp][32 ic][9 tap]
//   [41728, 50944)        sH2 [64][12][12]
#define REG2_OFF   H1_PAD
#define SH2_OFF    (H1_PAD + 18432)
#define SMEM_FLOATS (H1_PAD + 18432 + H2_PER)   // 50944
#define SMEM_BYTES  (SMEM_FLOATS * 4)           // 203776

// ---------------------------------------------------------------------------
// f32x2 packed helpers (FFMA2 path — only reachable via PTX)
// ---------------------------------------------------------------------------
__device__ __forceinline__ ull fma2(ull a, ull b, ull c) {
    ull d;
    asm("fma.rn.f32x2 %0, %1, %2, %3;" : "=l"(d) : "l"(a), "l"(b), "l"(c));
    return d;
}
__device__ __forceinline__ ull dup2(float v) {
    ull r;
    asm("mov.b64 %0, {%1, %1};" : "=l"(r) : "f"(v));
    return r;
}
__device__ __forceinline__ void unpack2(ull v, float& lo, float& hi) {
    asm("mov.b64 {%0, %1}, %2;" : "=f"(lo), "=f"(hi) : "l"(v));
}

// ---------------------------------------------------------------------------
// Full 4x4 conv tile, one ic, 2 oc-pairs (phase 1).
// ---------------------------------------------------------------------------
__device__ __forceinline__ void conv_tile_4oc(
    const float* __restrict__ base, const int rs,
    const ull* __restrict__ wA, const ull* __restrict__ wB,
    ull* __restrict__ accA, ull* __restrict__ accB)
{
    #pragma unroll
    for (int r = 0; r < 6; r++) {
        float d[6];
        {
            const float4 q0 = *reinterpret_cast<const float4*>(base + r * rs);
            const float2 q1 = *reinterpret_cast<const float2*>(base + r * rs + 4);
            d[0] = q0.x; d[1] = q0.y; d[2] = q0.z; d[3] = q0.w;
            d[4] = q1.x; d[5] = q1.y;
        }
        #pragma unroll
        for (int dc = 0; dc < 6; dc++) {
            const ull dd = dup2(d[dc]);
            #pragma unroll
            for (int ky = 0; ky < 3; ky++) {
                const int ar = r - ky;
                if (ar >= 0 && ar < 4) {
                    #pragma unroll
                    for (int kx = 0; kx < 3; kx++) {
                        const int ac = dc - kx;
                        if (ac >= 0 && ac < 4) {
                            accA[ar * 4 + ac] = fma2(dd, wA[ky * 3 + kx], accA[ar * 4 + ac]);
                            accB[ar * 4 + ac] = fma2(dd, wB[ky * 3 + kx], accB[ar * 4 + ac]);
                        }
                    }
                }
            }
        }
    }
}

// ---------------------------------------------------------------------------
// Half tile: 2 conv rows x 4 conv cols (patch 4x6), one ic, 2 oc-pairs.
// ---------------------------------------------------------------------------
__device__ __forceinline__ void conv_half_4oc(
    const float* __restrict__ base, const int rs,
    const ull* __restrict__ wA, const ull* __restrict__ wB,
    ull* __restrict__ accA, ull* __restrict__ accB)
{
    #pragma unroll
    for (int r = 0; r < 4; r++) {
        float d[6];
        {
            const float4 q0 = *reinterpret_cast<const float4*>(base + r * rs);
            const float2 q1 = *reinterpret_cast<const float2*>(base + r * rs + 4);
            d[0] = q0.x; d[1] = q0.y; d[2] = q0.z; d[3] = q0.w;
            d[4] = q1.x; d[5] = q1.y;
        }
        #pragma unroll
        for (int dc = 0; dc < 6; dc++) {
            const ull dd = dup2(d[dc]);
            #pragma unroll
            for (int ky = 0; ky < 3; ky++) {
                const int ar = r - ky;
                if (ar >= 0 && ar < 2) {
                    #pragma unroll
                    for (int kx = 0; kx < 3; kx++) {
                        const int ac = dc - kx;
                        if (ac >= 0 && ac < 4) {
                            accA[ar * 4 + ac] = fma2(dd, wA[ky * 3 + kx], accA[ar * 4 + ac]);
                            accB[ar * 4 + ac] = fma2(dd, wB[ky * 3 + kx], accB[ar * 4 + ac]);
                        }
                    }
                }
            }
        }
    }
}

// pool(2x2)+relu+store the 2x2 pooled outputs of a full 4x4 tile (one oc-pair)
__device__ __forceinline__ void pool_store_2oc(
    float* __restrict__ dst, const ull* __restrict__ acc,
    int pair, int plane, int rs, int py0, int px0)
{
    #pragma unroll
    for (int i = 0; i < 2; i++) {
        #pragma unroll
        for (int j = 0; j < 2; j++) {
            float l0, h0, l1, h1, l2, h2, l3, h3;
            unpack2(acc[(2 * i) * 4 + 2 * j],         l0, h0);
            unpack2(acc[(2 * i) * 4 + 2 * j + 1],     l1, h1);
            unpack2(acc[(2 * i + 1) * 4 + 2 * j],     l2, h2);
            unpack2(acc[(2 * i + 1) * 4 + 2 * j + 1], l3, h3);
            const float mlo = fmaxf(fmaxf(l0, l1), fmaxf(l2, l3));
            const float mhi = fmaxf(fmaxf(h0, h1), fmaxf(h2, h3));
            dst[(2 * pair)     * plane + (py0 + i) * rs + (px0 + j)] = fmaxf(mlo, 0.f);
            dst[(2 * pair + 1) * plane + (py0 + i) * rs + (px0 + j)] = fmaxf(mhi, 0.f);
        }
    }
}

// pool(2x2)+relu+store 1 pooled row x 2 pooled cols from a 2x4 half tile
__device__ __forceinline__ void pool_store_half(
    float* __restrict__ dst, const ull* __restrict__ acc,
    int pair, int plane, int rs, int pr, int pc0)
{
    #pragma unroll
    for (int j = 0; j < 2; j++) {
        float l0, h0, l1, h1, l2, h2, l3, h3;
        unpack2(acc[2 * j],         l0, h0);
        unpack2(acc[2 * j + 1],     l1, h1);
        unpack2(acc[4 + 2 * j],     l2, h2);
        unpack2(acc[4 + 2 * j + 1], l3, h3);
        const float mlo = fmaxf(fmaxf(l0, l1), fmaxf(l2, l3));
        const float mhi = fmaxf(fmaxf(h0, h1), fmaxf(h2, h3));
        dst[(2 * pair)     * plane + pr * rs + pc0 + j] = fmaxf(mlo, 0.f);
        dst[(2 * pair + 1) * plane + pr * rs + pc0 + j] = fmaxf(mhi, 0.f);
    }
}

// ---------------------------------------------------------------------------
// Fused kernel: one block per image.
// ---------------------------------------------------------------------------
__global__ __launch_bounds__(NTHREADS, 1) void qp_fused_kernel(
    const float* __restrict__ x,
    const float* __restrict__ w1g, const float* __restrict__ b1g,
    const float* __restrict__ w2g, const float* __restrict__ b2g,
    const float* __restrict__ fw,  const float* __restrict__ fb,
    float* __restrict__ out)
{
    extern __shared__ float smem[];
    float* sH1  = smem;                 // padded [32][26][28]
    float* sImg = smem + REG2_OFF;      // phase1 alias: padded image [3][54][56]
    float* sW2f = smem + REG2_OFF;      // later: conv2 weights ull2[16][32][9]
    float* sH2  = smem + SH2_OFF;       // [64][12][12]

    __shared__ __align__(16) float sW1f[864];   // conv1 weights ull2[8][3][9]
    __shared__ float2 sB1[16];
    __shared__ float2 sB2[32];
    __shared__ float  sRed[12][6];

    const int tid  = threadIdx.x;
    const int bimg = blockIdx.x;
    const float* xp = x + (size_t)bimg * X_COLS;

    // ---- stage image (padded rows) + conv1 weights (grouped ull2 taps) ----
    for (int i = tid; i < N_IMG; i += NTHREADS) {
        const int ic = i / (IMG_HW * IMG_HW);
        const int rm = i % (IMG_HW * IMG_HW);
        sImg[ic * IMG_PL + (rm / IMG_HW) * IMG_RS + (rm % IMG_HW)] = xp[i];
    }
    // w1 layout: l = oc*27 + ic*9 + tap  ->  [g=oc/4][ic][tap][pairsel][oc&1]
    for (int l = tid; l < 864; l += NTHREADS) {
        const int oc = l / 27, r = l % 27;
        const int g = oc >> 2, psel = (oc >> 1) & 1;
        sW1f[(((g * 3 + r / 9) * 9 + r % 9) * 2 + psel) * 2 + (oc & 1)] = w1g[l];
    }
    if (tid < 16) sB1[tid] = make_float2(b1g[2 * tid], b1g[2 * tid + 1]);
    if (tid < 32) sB2[tid] = make_float2(b2g[2 * tid], b2g[2 * tid + 1]);
    __syncthreads();

    // ---- phase 1: conv1 (3->32) + relu + pool ----
    // items: 8 groups (4 oc) x 169 full tiles = 1352
    {
        const ulonglong2* sW1 = reinterpret_cast<const ulonglong2*>(sW1f);
        const ull* sB1u = reinterpret_cast<const ull*>(sB1);
        for (int idx = tid; idx < 1352; idx += NTHREADS) {
            const int g = idx / 169, t = idx % 169;
            const int ty = t / 13, tx = t % 13;
            ull accA[16], accB[16];
            const ull bzA = sB1u[2 * g], bzB = sB1u[2 * g + 1];
            #pragma unroll
            for (int k = 0; k < 16; k++) { accA[k] = bzA; accB[k] = bzB; }
            #pragma unroll
            for (int ic = 0; ic < 3; ic++) {
                ull wA[9], wB[9];
                const ulonglong2* wp = sW1 + (g * 3 + ic) * 9;
                #pragma unroll
                for (int k = 0; k < 9; k++) {
                    const ulonglong2 wv = wp[k];
                    wA[k] = wv.x; wB[k] = wv.y;
                }
                conv_tile_4oc(sImg + ic * IMG_PL + (ty * 4) * IMG_RS + tx * 4,
                              IMG_RS, wA, wB, accA, accB);
            }
            pool_store_2oc(sH1, accA, 2 * g,     H1_PL, H1_RS, ty * 2, tx * 2);
            pool_store_2oc(sH1, accB, 2 * g + 1, H1_PL, H1_RS, ty * 2, tx * 2);
        }
    }
    __syncthreads();

    // ---- stage conv2 weights (grouped ull2 taps; overwrites image) ----
    // w2 layout: l = oc*288 + ic*9 + tap -> [g=oc/4][ic][tap][pairsel][oc&1]
    for (int l4 = tid * 4; l4 < 18432; l4 += NTHREADS * 4) {
        const float4 v = *reinterpret_cast<const float4*>(w2g + l4);
        const float e[4] = {v.x, v.y, v.z, v.w};
        #pragma unroll
        for (int k = 0; k < 4; k++) {
            const int l = l4 + k;
            const int oc = l / 288, r = l % 288;
            const int g = oc >> 2, psel = (oc >> 1) & 1;
            sW2f[(((g * 32 + r / 9) * 9 + r % 9) * 2 + psel) * 2 + (oc & 1)] = e[k];
        }
    }
    __syncthreads();

    // ---- phase 2: conv2 (32->64) + relu + pool ----
    // Thread t owns oc-group g = t%16 and 3 spatial half-tiles
    // {pbase, pbase+24, pbase+48} (pbase = t/16 in [0,24)).
    // Weights for (g, ic) are loaded ONCE per ic and reused for all 3 tiles.
    {
        const ulonglong2* sW2 = reinterpret_cast<const ulonglong2*>(sW2f);
        const ull* sB2u = reinterpret_cast<const ull*>(sB2);

        const int g = tid & 15;
        const int pbase = tid >> 4;          // 0..23
        int prk[3], ctk[3];
        const float* dptr[3];
        #pragma unroll
        for (int k = 0; k < 3; k++) {
            const int p = pbase + 24 * k;    // 0..71
            prk[k] = p / 6; ctk[k] = p % 6;
            dptr[k] = sH1 + (2 * prk[k]) * H1_RS + ctk[k] * 4;
        }

        ull acc[3][16];                       // [k][A:0..7 | B:8..15]
        const ull bzA = sB2u[2 * g], bzB = sB2u[2 * g + 1];
        #pragma unroll
        for (int k = 0; k < 3; k++) {
            #pragma unroll
            for (int j = 0; j < 8; j++) { acc[k][j] = bzA; acc[k][8 + j] = bzB; }
        }

        #pragma unroll 1
        for (int ic = 0; ic < 32; ic++) {
            ull wA[9], wB[9];
            const ulonglong2* wp = sW2 + (g * 32 + ic) * 9;
            #pragma unroll
            for (int k = 0; k < 9; k++) {
                const ulonglong2 wv = wp[k];
                wA[k] = wv.x; wB[k] = wv.y;
            }
            #pragma unroll
            for (int k = 0; k < 3; k++) {
                conv_half_4oc(dptr[k] + ic * H1_PL, H1_RS,
                              wA, wB, acc[k], acc[k] + 8);
            }
        }
        #pragma unroll
        for (int k = 0; k < 3; k++) {
            pool_store_half(sH2, acc[k],     2 * g,     P2 * P2, P2, prk[k], ctk[k] * 2);
            pool_store_half(sH2, acc[k] + 8, 2 * g + 1, P2 * P2, P2, prk[k], ctk[k] * 2);
        }
    }
    __syncthreads();

    // ---- phase 3: fcn (6 x 9219) + relu ----
    {
        float acc[6] = {0.f, 0.f, 0.f, 0.f, 0.f, 0.f};
        for (int j = tid; j < H2_PER; j += NTHREADS) {
            const float hv = sH2[j];
            #pragma unroll
            for (int o = 0; o < 6; o++)
                acc[o] = fmaf(hv, __ldg(fw + o * FCN_IN + j), acc[o]);
        }
        #pragma unroll
        for (int off = 16; off > 0; off >>= 1) {
            #pragma unroll
            for (int o = 0; o < 6; o++)
                acc[o] += __shfl_xor_sync(0xFFFFFFFFu, acc[o], off);
        }
        const int warp = tid >> 5, lane = tid & 31;
        if (lane == 0) {
            #pragma unroll
            for (int o = 0; o < 6; o++) sRed[warp][o] = acc[o];
        }
    }
    __syncthreads();

    if (tid == 0) {
        float yv[6];
        #pragma unroll
        for (int o = 0; o < 6; o++) {
            float s = 0.f;
            #pragma unroll
            for (int w = 0; w < 12; w++) s += sRed[w][o];
            #pragma unroll
            for (int k = 0; k < 3; k++)
                s = fmaf(xp[N_IMG + k], fw[o * FCN_IN + H2_PER + k], s);
            yv[o] = fmaxf(s + fb[o], 0.f);
        }

        // ---- double-precision 2x2 SVD clip + KKT (Schur) solve ----
        double A00 = yv[0], A01 = yv[1], A10 = yv[2], A11 = yv[3];
        const double b0 = yv[4], b1v = yv[5];

        const double E = 0.5 * (A00 + A11), F = 0.5 * (A00 - A11);
        const double G = 0.5 * (A10 + A01), H = 0.5 * (A10 - A01);
        const double Qh = sqrt(E * E + H * H);
        const double Rh = sqrt(F * F + G * G);
        const double s1 = Qh + Rh;
        const double s2 = fabs(Qh - Rh);

        if (s1 < 1e-300) {
            A00 = 0.01; A01 = 0.0; A10 = 0.0; A11 = 0.01;
        } else {
            const double s2c = fmax(s2, 0.1 * s1);
            if (s2c > s2) {
                const double p = A00 * A00 + A10 * A10;
                const double r = A01 * A01 + A11 * A11;
                const double q = A00 * A01 + A10 * A11;
                const double f = 0.5 * (p - r);
                const double disc = sqrt(f * f + q * q);
                double v1x, v1y;
                if (f >= 0.0) { v1x = disc + f; v1y = q; }
                else          { v1x = q;        v1y = disc - f; }
                double inv = 1.0 / sqrt(fmax(v1x * v1x + v1y * v1y, 1e-300));
                v1x *= inv; v1y *= inv;
                double v2x = -v1y, v2y = v1x;

                const double pB = A00 * A00 + A01 * A01;
                const double rB = A10 * A10 + A11 * A11;
                const double qB = A00 * A10 + A01 * A11;
                const double fB = 0.5 * (pB - rB);
                const double discB = sqrt(fB * fB + qB * qB);
                double u1x, u1y;
                if (fB >= 0.0) { u1x = discB + fB; u1y = qB; }
                else           { u1x = qB;         u1y = discB - fB; }
                inv = 1.0 / sqrt(fmax(u1x * u1x + u1y * u1y, 1e-300));
                u1x *= inv; u1y *= inv;
                double u2x = -u1y, u2y = u1x;

                const double tsgn = u2x * (A00 * v2x + A01 * v2y)
                                  + u2y * (A10 * v2x + A11 * v2y);
                if (tsgn < 0.0) { v2x = -v2x; v2y = -v2y; }

                const double d = s2c - s2;
                A00 += d * u2x * v2x; A01 += d * u2x * v2y;
                A10 += d * u2y * v2x; A11 += d * u2y * v2y;
            }
        }

        const double qi0 = 1.0, qi1 = 2.0;
        const double S00 = A00 * A00 * qi0 + A01 * A01 * qi1;
        const double S01 = A00 * A10 * qi0 + A01 * A11 * qi1;
        const double S11 = A10 * A10 * qi0 + A11 * A11 * qi1;
        const double r0 = A01 * 2000.0 - b0;
        const double r1 = A11 * 2000.0 - b1v;
        const double idet = 1.0 / (S00 * S11 - S01 * S01);
        const double l0 = (S11 * r0 - S01 * r1) * idet;
        const double l1 = (S00 * r1 - S01 * r0) * idet;
        out[bimg * 2 + 0] = (float)(-qi0 * (A00 * l0 + A10 * l1));
        out[bimg * 2 + 1] = (float)(2000.0 - qi1 * (A01 * l0 + A11 * l1));
    }
}

// ---------------------------------------------------------------------------
// Launcher (graph-capturable)
// ---------------------------------------------------------------------------
extern "C" void kernel_launch(void* const* d_in, const int* in_sizes, int n_in,
                              void* d_out, int out_size)
{
    const float* x  = (const float*)d_in[0];
    const float* w1 = (const float*)d_in[1];
    const float* b1 = (const float*)d_in[2];
    const float* w2 = (const float*)d_in[3];
    const float* b2 = (const float*)d_in[4];
    const float* fw = (const float*)d_in[5];
    const float* fb = (const float*)d_in[6];
    float* out = (float*)d_out;

    cudaFuncSetAttribute(qp_fused_kernel,
                         cudaFuncAttributeMaxDynamicSharedMemorySize, SMEM_BYTES);
    qp_fused_kernel<<<BATCH, NTHREADS, SMEM_BYTES>>>(x, w1, b1, w2, b2, fw, fb, out);
}

// round 12
// speedup vs baseline: 1.1895x; 1.1895x over previous
#include <cuda_runtime.h>
#include <cuda_bf16.h>
#include <math.h>

typedef unsigned long long ull;

// ---------------------------------------------------------------------------
// Problem constants
// ---------------------------------------------------------------------------
#define BATCH     1024
#define X_COLS    8751
#define N_IMG     8748          // 3*54*54
#define IMG_HW    54
#define IMG_RS    56            // padded image row stride (floats, 16B aligned)
#define IMG_PL    (IMG_HW * IMG_RS)     // 3024 per channel

#define P1        26
#define H1_RS     28            // padded H1 row stride
#define H1_PL     (P1 * H1_RS)          // 728 per channel
#define H1_PAD    (32 * H1_PL)          // 23296 floats

#define P2        12
#define H2_PER    (64 * P2 * P2)        // 9216

#define FCN_IN    9219
#define NTHREADS  384

// conv2 weights: ull2[16 grp][289]  (288 = 32 ic * 9 taps, +1 pad ull2 per
// group so g-stride = 4624 B != 0 mod 128 -> no cross-g bank aliasing)
#define W2_GSTRIDE 289
#define W2_FLOATS  (16 * W2_GSTRIDE * 4)        // 18496

// dynamic smem (floats):
//   [0, 23296)            sH1 padded [32][26][28]
//   [23296, 23296+18496)  region2: phase1 = padded image [3][54][56] (9072);
//                         then conv2 weights ull2[16][289]
//   [41792, 51008)        sH2 [64][12][12]
#define REG2_OFF   H1_PAD
#define SH2_OFF    (H1_PAD + W2_FLOATS)
#define SMEM_FLOATS (H1_PAD + W2_FLOATS + H2_PER)   // 51008
#define SMEM_BYTES  (SMEM_FLOATS * 4)               // 204032

// ---------------------------------------------------------------------------
// f32x2 packed helpers (FFMA2 path — only reachable via PTX)
// ---------------------------------------------------------------------------
__device__ __forceinline__ ull fma2(ull a, ull b, ull c) {
    ull d;
    asm("fma.rn.f32x2 %0, %1, %2, %3;" : "=l"(d) : "l"(a), "l"(b), "l"(c));
    return d;
}
__device__ __forceinline__ ull dup2(float v) {
    ull r;
    asm("mov.b64 %0, {%1, %1};" : "=l"(r) : "f"(v));
    return r;
}
__device__ __forceinline__ void unpack2(ull v, float& lo, float& hi) {
    asm("mov.b64 {%0, %1}, %2;" : "=f"(lo), "=f"(hi) : "l"(v));
}

// ---------------------------------------------------------------------------
// Full 4x4 conv tile, one ic, 2 oc-pairs (phase 1).
// ---------------------------------------------------------------------------
__device__ __forceinline__ void conv_tile_4oc(
    const float* __restrict__ base, const int rs,
    const ull* __restrict__ wA, const ull* __restrict__ wB,
    ull* __restrict__ accA, ull* __restrict__ accB)
{
    #pragma unroll
    for (int r = 0; r < 6; r++) {
        float d[6];
        {
            const float4 q0 = *reinterpret_cast<const float4*>(base + r * rs);
            const float2 q1 = *reinterpret_cast<const float2*>(base + r * rs + 4);
            d[0] = q0.x; d[1] = q0.y; d[2] = q0.z; d[3] = q0.w;
            d[4] = q1.x; d[5] = q1.y;
        }
        #pragma unroll
        for (int dc = 0; dc < 6; dc++) {
            const ull dd = dup2(d[dc]);
            #pragma unroll
            for (int ky = 0; ky < 3; ky++) {
                const int ar = r - ky;
                if (ar >= 0 && ar < 4) {
                    #pragma unroll
                    for (int kx = 0; kx < 3; kx++) {
                        const int ac = dc - kx;
                        if (ac >= 0 && ac < 4) {
                            accA[ar * 4 + ac] = fma2(dd, wA[ky * 3 + kx], accA[ar * 4 + ac]);
                            accB[ar * 4 + ac] = fma2(dd, wB[ky * 3 + kx], accB[ar * 4 + ac]);
                        }
                    }
                }
            }
        }
    }
}

// ---------------------------------------------------------------------------
// Half tile: 2 conv rows x 4 conv cols (patch 4x6), one ic, 2 oc-pairs.
// ---------------------------------------------------------------------------
__device__ __forceinline__ void conv_half_4oc(
    const float* __restrict__ base, const int rs,
    const ull* __restrict__ wA, const ull* __restrict__ wB,
    ull* __restrict__ accA, ull* __restrict__ accB)
{
    #pragma unroll
    for (int r = 0; r < 4; r++) {
        float d[6];
        {
            const float4 q0 = *reinterpret_cast<const float4*>(base + r * rs);
            const float2 q1 = *reinterpret_cast<const float2*>(base + r * rs + 4);
            d[0] = q0.x; d[1] = q0.y; d[2] = q0.z; d[3] = q0.w;
            d[4] = q1.x; d[5] = q1.y;
        }
        #pragma unroll
        for (int dc = 0; dc < 6; dc++) {
            const ull dd = dup2(d[dc]);
            #pragma unroll
            for (int ky = 0; ky < 3; ky++) {
                const int ar = r - ky;
                if (ar >= 0 && ar < 2) {
                    #pragma unroll
                    for (int kx = 0; kx < 3; kx++) {
                        const int ac = dc - kx;
                        if (ac >= 0 && ac < 4) {
                            accA[ar * 4 + ac] = fma2(dd, wA[ky * 3 + kx], accA[ar * 4 + ac]);
                            accB[ar * 4 + ac] = fma2(dd, wB[ky * 3 + kx], accB[ar * 4 + ac]);
                        }
                    }
                }
            }
        }
    }
}

// pool(2x2)+relu+store the 2x2 pooled outputs of a full 4x4 tile (one oc-pair)
__device__ __forceinline__ void pool_store_2oc(
    float* __restrict__ dst, const ull* __restrict__ acc,
    int pair, int plane, int rs, int py0, int px0)
{
    #pragma unroll
    for (int i = 0; i < 2; i++) {
        #pragma unroll
        for (int j = 0; j < 2; j++) {
            float l0, h0, l1, h1, l2, h2, l3, h3;
            unpack2(acc[(2 * i) * 4 + 2 * j],         l0, h0);
            unpack2(acc[(2 * i) * 4 + 2 * j + 1],     l1, h1);
            unpack2(acc[(2 * i + 1) * 4 + 2 * j],     l2, h2);
            unpack2(acc[(2 * i + 1) * 4 + 2 * j + 1], l3, h3);
            const float mlo = fmaxf(fmaxf(l0, l1), fmaxf(l2, l3));
            const float mhi = fmaxf(fmaxf(h0, h1), fmaxf(h2, h3));
            dst[(2 * pair)     * plane + (py0 + i) * rs + (px0 + j)] = fmaxf(mlo, 0.f);
            dst[(2 * pair + 1) * plane + (py0 + i) * rs + (px0 + j)] = fmaxf(mhi, 0.f);
        }
    }
}

// pool(2x2)+relu+store 1 pooled row x 2 pooled cols from a 2x4 half tile
__device__ __forceinline__ void pool_store_half(
    float* __restrict__ dst, const ull* __restrict__ acc,
    int pair, int plane, int rs, int pr, int pc0)
{
    #pragma unroll
    for (int j = 0; j < 2; j++) {
        float l0, h0, l1, h1, l2, h2, l3, h3;
        unpack2(acc[2 * j],         l0, h0);
        unpack2(acc[2 * j + 1],     l1, h1);
        unpack2(acc[4 + 2 * j],     l2, h2);
        unpack2(acc[4 + 2 * j + 1], l3, h3);
        const float mlo = fmaxf(fmaxf(l0, l1), fmaxf(l2, l3));
        const float mhi = fmaxf(fmaxf(h0, h1), fmaxf(h2, h3));
        dst[(2 * pair)     * plane + pr * rs + pc0 + j] = fmaxf(mlo, 0.f);
        dst[(2 * pair + 1) * plane + pr * rs + pc0 + j] = fmaxf(mhi, 0.f);
    }
}

// ---------------------------------------------------------------------------
// Fused kernel: one block per image.
// ---------------------------------------------------------------------------
__global__ __launch_bounds__(NTHREADS, 1) void qp_fused_kernel(
    const float* __restrict__ x,
    const float* __restrict__ w1g, const float* __restrict__ b1g,
    const float* __restrict__ w2g, const float* __restrict__ b2g,
    const float* __restrict__ fw,  const float* __restrict__ fb,
    float* __restrict__ out)
{
    extern __shared__ float smem[];
    float* sH1  = smem;                 // padded [32][26][28]
    float* sImg = smem + REG2_OFF;      // phase1 alias: padded image [3][54][56]
    float* sW2f = smem + REG2_OFF;      // later: conv2 weights ull2[16][289]
    float* sH2  = smem + SH2_OFF;       // [64][12][12]

    __shared__ __align__(16) float sW1f[864];   // conv1 weights ull2[8][3][9]
    __shared__ float2 sB1[16];
    __shared__ float2 sB2[32];
    __shared__ float  sRed[12][6];

    const int tid  = threadIdx.x;
    const int bimg = blockIdx.x;
    const float* xp = x + (size_t)bimg * X_COLS;

    // ---- stage image (padded rows) + conv1 weights (grouped ull2 taps) ----
    for (int i = tid; i < N_IMG; i += NTHREADS) {
        const int ic = i / (IMG_HW * IMG_HW);
        const int rm = i % (IMG_HW * IMG_HW);
        sImg[ic * IMG_PL + (rm / IMG_HW) * IMG_RS + (rm % IMG_HW)] = xp[i];
    }
    // w1 layout: l = oc*27 + ic*9 + tap  ->  [g=oc/4][ic][tap][pairsel][oc&1]
    for (int l = tid; l < 864; l += NTHREADS) {
        const int oc = l / 27, r = l % 27;
        const int g = oc >> 2, psel = (oc >> 1) & 1;
        sW1f[(((g * 3 + r / 9) * 9 + r % 9) * 2 + psel) * 2 + (oc & 1)] = w1g[l];
    }
    if (tid < 16) sB1[tid] = make_float2(b1g[2 * tid], b1g[2 * tid + 1]);
    if (tid < 32) sB2[tid] = make_float2(b2g[2 * tid], b2g[2 * tid + 1]);
    __syncthreads();

    // ---- phase 1: conv1 (3->32) + relu + pool ----
    // items: 8 groups (4 oc) x 169 full tiles = 1352
    {
        const ulonglong2* sW1 = reinterpret_cast<const ulonglong2*>(sW1f);
        const ull* sB1u = reinterpret_cast<const ull*>(sB1);
        for (int idx = tid; idx < 1352; idx += NTHREADS) {
            const int g = idx / 169, t = idx % 169;
            const int ty = t / 13, tx = t % 13;
            ull accA[16], accB[16];
            const ull bzA = sB1u[2 * g], bzB = sB1u[2 * g + 1];
            #pragma unroll
            for (int k = 0; k < 16; k++) { accA[k] = bzA; accB[k] = bzB; }
            #pragma unroll
            for (int ic = 0; ic < 3; ic++) {
                ull wA[9], wB[9];
                const ulonglong2* wp = sW1 + (g * 3 + ic) * 9;
                #pragma unroll
                for (int k = 0; k < 9; k++) {
                    const ulonglong2 wv = wp[k];
                    wA[k] = wv.x; wB[k] = wv.y;
                }
                conv_tile_4oc(sImg + ic * IMG_PL + (ty * 4) * IMG_RS + tx * 4,
                              IMG_RS, wA, wB, accA, accB);
            }
            pool_store_2oc(sH1, accA, 2 * g,     H1_PL, H1_RS, ty * 2, tx * 2);
            pool_store_2oc(sH1, accB, 2 * g + 1, H1_PL, H1_RS, ty * 2, tx * 2);
        }
    }
    __syncthreads();

    // ---- stage conv2 weights (grouped ull2 taps, padded; overwrites image) ----
    // w2 layout: l = oc*288 + ic*9 + tap -> ull2 index g*289 + ic*9 + tap,
    //            float offset psel*2 + (oc&1) inside the 16B ull2.
    for (int l4 = tid * 4; l4 < 18432; l4 += NTHREADS * 4) {
        const float4 v = *reinterpret_cast<const float4*>(w2g + l4);
        const float e[4] = {v.x, v.y, v.z, v.w};
        #pragma unroll
        for (int k = 0; k < 4; k++) {
            const int l = l4 + k;
            const int oc = l / 288, r = l % 288;
            const int g = oc >> 2, psel = (oc >> 1) & 1;
            sW2f[(g * W2_GSTRIDE + r) * 4 + psel * 2 + (oc & 1)] = e[k];
        }
    }
    __syncthreads();

    // ---- phase 2: conv2 (32->64) + relu + pool ----
    // Thread t: oc-group g = t/24 (uniform over 24-lane chunks), pos = t%24,
    // 3 half-tiles {pos, pos+24, pos+48}. Weights loaded ONCE per ic for all 3.
    {
        const ulonglong2* sW2 = reinterpret_cast<const ulonglong2*>(sW2f);
        const ull* sB2u = reinterpret_cast<const ull*>(sB2);

        const int g = tid / 24;              // 0..15, warp-chunk uniform
        const int pos = tid % 24;            // 0..23
        int prk[3], ctk[3];
        const float* dptr[3];
        #pragma unroll
        for (int k = 0; k < 3; k++) {
            const int p = pos + 24 * k;      // 0..71
            prk[k] = p / 6; ctk[k] = p % 6;
            dptr[k] = sH1 + (2 * prk[k]) * H1_RS + ctk[k] * 4;
        }

        ull acc[3][16];                      // [k][A:0..7 | B:8..15]
        const ull bzA = sB2u[2 * g], bzB = sB2u[2 * g + 1];
        #pragma unroll
        for (int k = 0; k < 3; k++) {
            #pragma unroll
            for (int j = 0; j < 8; j++) { acc[k][j] = bzA; acc[k][8 + j] = bzB; }
        }

        #pragma unroll 1
        for (int ic = 0; ic < 32; ic++) {
            ull wA[9], wB[9];
            const ulonglong2* wp = sW2 + g * W2_GSTRIDE + ic * 9;
            #pragma unroll
            for (int k = 0; k < 9; k++) {
                const ulonglong2 wv = wp[k];
                wA[k] = wv.x; wB[k] = wv.y;
            }
            #pragma unroll
            for (int k = 0; k < 3; k++) {
                conv_half_4oc(dptr[k] + ic * H1_PL, H1_RS,
                              wA, wB, acc[k], acc[k] + 8);
            }
        }
        #pragma unroll
        for (int k = 0; k < 3; k++) {
            pool_store_half(sH2, acc[k],     2 * g,     P2 * P2, P2, prk[k], ctk[k] * 2);
            pool_store_half(sH2, acc[k] + 8, 2 * g + 1, P2 * P2, P2, prk[k], ctk[k] * 2);
        }
    }
    __syncthreads();

    // ---- phase 3: fcn (6 x 9219) + relu ----
    {
        float acc[6] = {0.f, 0.f, 0.f, 0.f, 0.f, 0.f};
        for (int j = tid; j < H2_PER; j += NTHREADS) {
            const float hv = sH2[j];
            #pragma unroll
            for (int o = 0; o < 6; o++)
                acc[o] = fmaf(hv, __ldg(fw + o * FCN_IN + j), acc[o]);
        }
        #pragma unroll
        for (int off = 16; off > 0; off >>= 1) {
            #pragma unroll
            for (int o = 0; o < 6; o++)
                acc[o] += __shfl_xor_sync(0xFFFFFFFFu, acc[o], off);
        }
        const int warp = tid >> 5, lane = tid & 31;
        if (lane == 0) {
            #pragma unroll
            for (int o = 0; o < 6; o++) sRed[warp][o] = acc[o];
        }
    }
    __syncthreads();

    if (tid == 0) {
        float yv[6];
        #pragma unroll
        for (int o = 0; o < 6; o++) {
            float s = 0.f;
            #pragma unroll
            for (int w = 0; w < 12; w++) s += sRed[w][o];
            #pragma unroll
            for (int k = 0; k < 3; k++)
                s = fmaf(xp[N_IMG + k], fw[o * FCN_IN + H2_PER + k], s);
            yv[o] = fmaxf(s + fb[o], 0.f);
        }

        // ---- double-precision 2x2 SVD clip + KKT (Schur) solve ----
        double A00 = yv[0], A01 = yv[1], A10 = yv[2], A11 = yv[3];
        const double b0 = yv[4], b1v = yv[5];

        const double E = 0.5 * (A00 + A11), F = 0.5 * (A00 - A11);
        const double G = 0.5 * (A10 + A01), H = 0.5 * (A10 - A01);
        const double Qh = sqrt(E * E + H * H);
        const double Rh = sqrt(F * F + G * G);
        const double s1 = Qh + Rh;
        const double s2 = fabs(Qh - Rh);

        if (s1 < 1e-300) {
            A00 = 0.01; A01 = 0.0; A10 = 0.0; A11 = 0.01;
        } else {
            const double s2c = fmax(s2, 0.1 * s1);
            if (s2c > s2) {
                const double p = A00 * A00 + A10 * A10;
                const double r = A01 * A01 + A11 * A11;
                const double q = A00 * A01 + A10 * A11;
                const double f = 0.5 * (p - r);
                const double disc = sqrt(f * f + q * q);
                double v1x, v1y;
                if (f >= 0.0) { v1x = disc + f; v1y = q; }
                else          { v1x = q;        v1y = disc - f; }
                double inv = 1.0 / sqrt(fmax(v1x * v1x + v1y * v1y, 1e-300));
                v1x *= inv; v1y *= inv;
                double v2x = -v1y, v2y = v1x;

                const double pB = A00 * A00 + A01 * A01;
                const double rB = A10 * A10 + A11 * A11;
                const double qB = A00 * A10 + A01 * A11;
                const double fB = 0.5 * (pB - rB);
                const double discB = sqrt(fB * fB + qB * qB);
                double u1x, u1y;
                if (fB >= 0.0) { u1x = discB + fB; u1y = qB; }
                else           { u1x = qB;         u1y = discB - fB; }
                inv = 1.0 / sqrt(fmax(u1x * u1x + u1y * u1y, 1e-300));
                u1x *= inv; u1y *= inv;
                double u2x = -u1y, u2y = u1x;

                const double tsgn = u2x * (A00 * v2x + A01 * v2y)
                                  + u2y * (A10 * v2x + A11 * v2y);
                if (tsgn < 0.0) { v2x = -v2x; v2y = -v2y; }

                const double d = s2c - s2;
                A00 += d * u2x * v2x; A01 += d * u2x * v2y;
                A10 += d * u2y * v2x; A11 += d * u2y * v2y;
            }
        }

        const double qi0 = 1.0, qi1 = 2.0;
        const double S00 = A00 * A00 * qi0 + A01 * A01 * qi1;
        const double S01 = A00 * A10 * qi0 + A01 * A11 * qi1;
        const double S11 = A10 * A10 * qi0 + A11 * A11 * qi1;
        const double r0 = A01 * 2000.0 - b0;
        const double r1 = A11 * 2000.0 - b1v;
        const double idet = 1.0 / (S00 * S11 - S01 * S01);
        const double l0 = (S11 * r0 - S01 * r1) * idet;
        const double l1 = (S00 * r1 - S01 * r0) * idet;
        out[bimg * 2 + 0] = (float)(-qi0 * (A00 * l0 + A10 * l1));
        out[bimg * 2 + 1] = (float)(2000.0 - qi1 * (A01 * l0 + A11 * l1));
    }
}

// ---------------------------------------------------------------------------
// Launcher (graph-capturable)
// ---------------------------------------------------------------------------
extern "C" void kernel_launch(void* const* d_in, const int* in_sizes, int n_in,
                              void* d_out, int out_size)
{
    const float* x  = (const float*)d_in[0];
    const float* w1 = (const float*)d_in[1];
    const float* b1 = (const float*)d_in[2];
    const float* w2 = (const float*)d_in[3];
    const float* b2 = (const float*)d_in[4];
    const float* fw = (const float*)d_in[5];
    const float* fb = (const float*)d_in[6];
    float* out = (float*)d_out;

    cudaFuncSetAttribute(qp_fused_kernel,
                         cudaFuncAttributeMaxDynamicSharedMemorySize, SMEM_BYTES);
    qp_fused_kernel<<<BATCH, NTHREADS, SMEM_BYTES>>>(x, w1, b1, w2, b2, fw, fb, out);
}

// round 15
// speedup vs baseline: 1.2172x; 1.0233x over previous
#include <cuda_runtime.h>
#include <cuda_bf16.h>
#include <math.h>

typedef unsigned long long ull;

// ---------------------------------------------------------------------------
// Problem constants
// ---------------------------------------------------------------------------
#define BATCH     1024
#define X_COLS    8751
#define N_IMG     8748          // 3*54*54
#define IMG_HW    54
#define IMG_RS    56            // padded image row stride (floats, 16B aligned)
#define IMG_PL    (IMG_HW * IMG_RS)     // 3024 per channel

#define P1        26
#define H1_RS     28            // padded H1 row stride
#define H1_PL     (P1 * H1_RS)          // 728 per channel
#define H1_PAD    (32 * H1_PL)          // 23296 floats

#define P2        12
#define H2_PER    (64 * P2 * P2)        // 9216

#define FCN_IN    9219
#define NTHREADS  384

// dynamic smem (floats):
//   [0, 23296)            sH1 padded [32][26][28]
//   [23296, 41728)        region2: phase1 = padded image [3][54][56] (9072);
//                         then conv2 weights as ull2[16 grp][32 ic][9 tap]
//   [41728, 50944)        sH2 [64][12][12]
#define REG2_OFF   H1_PAD
#define SH2_OFF    (H1_PAD + 18432)
#define SMEM_FLOATS (H1_PAD + 18432 + H2_PER)   // 50944
#define SMEM_BYTES  (SMEM_FLOATS * 4)           // 203776

// ---------------------------------------------------------------------------
// f32x2 packed helpers (FFMA2 path — only reachable via PTX)
// ---------------------------------------------------------------------------
__device__ __forceinline__ ull fma2(ull a, ull b, ull c) {
    ull d;
    asm("fma.rn.f32x2 %0, %1, %2, %3;" : "=l"(d) : "l"(a), "l"(b), "l"(c));
    return d;
}
__device__ __forceinline__ ull dup2(float v) {
    ull r;
    asm("mov.b64 %0, {%1, %1};" : "=l"(r) : "f"(v));
    return r;
}
__device__ __forceinline__ void unpack2(ull v, float& lo, float& hi) {
    asm("mov.b64 {%0, %1}, %2;" : "=f"(lo), "=f"(hi) : "l"(v));
}

// ---------------------------------------------------------------------------
// Full 4x4 conv tile, one ic, 2 oc-pairs (phase 1).
// ---------------------------------------------------------------------------
__device__ __forceinline__ void conv_tile_4oc(
    const float* __restrict__ base, const int rs,
    const ull* __restrict__ wA, const ull* __restrict__ wB,
    ull* __restrict__ accA, ull* __restrict__ accB)
{
    #pragma unroll
    for (int r = 0; r < 6; r++) {
        float d[6];
        {
            const float4 q0 = *reinterpret_cast<const float4*>(base + r * rs);
            const float2 q1 = *reinterpret_cast<const float2*>(base + r * rs + 4);
            d[0] = q0.x; d[1] = q0.y; d[2] = q0.z; d[3] = q0.w;
            d[4] = q1.x; d[5] = q1.y;
        }
        #pragma unroll
        for (int dc = 0; dc < 6; dc++) {
            const ull dd = dup2(d[dc]);
            #pragma unroll
            for (int ky = 0; ky < 3; ky++) {
                const int ar = r - ky;
                if (ar >= 0 && ar < 4) {
                    #pragma unroll
                    for (int kx = 0; kx < 3; kx++) {
                        const int ac = dc - kx;
                        if (ac >= 0 && ac < 4) {
                            accA[ar * 4 + ac] = fma2(dd, wA[ky * 3 + kx], accA[ar * 4 + ac]);
                            accB[ar * 4 + ac] = fma2(dd, wB[ky * 3 + kx], accB[ar * 4 + ac]);
                        }
                    }
                }
            }
        }
    }
}

// ---------------------------------------------------------------------------
// Half tile: 2 conv rows x 4 conv cols (patch 4x6), one ic, 2 oc-pairs.
// All 4 rows loaded UP FRONT (8 back-to-back LDS -> MLP=8, one exposed
// latency window per ic instead of four).
// ---------------------------------------------------------------------------
__device__ __forceinline__ void conv_half_4oc(
    const float* __restrict__ base, const int rs,
    const ull* __restrict__ wA, const ull* __restrict__ wB,
    ull* __restrict__ accA, ull* __restrict__ accB)
{
    float d[4][6];
    #pragma unroll
    for (int r = 0; r < 4; r++) {
        const float4 q0 = *reinterpret_cast<const float4*>(base + r * rs);
        const float2 q1 = *reinterpret_cast<const float2*>(base + r * rs + 4);
        d[r][0] = q0.x; d[r][1] = q0.y; d[r][2] = q0.z; d[r][3] = q0.w;
        d[r][4] = q1.x; d[r][5] = q1.y;
    }
    #pragma unroll
    for (int r = 0; r < 4; r++) {
        #pragma unroll
        for (int dc = 0; dc < 6; dc++) {
            const ull dd = dup2(d[r][dc]);
            #pragma unroll
            for (int ky = 0; ky < 3; ky++) {
                const int ar = r - ky;
                if (ar >= 0 && ar < 2) {
                    #pragma unroll
                    for (int kx = 0; kx < 3; kx++) {
                        const int ac = dc - kx;
                        if (ac >= 0 && ac < 4) {
                            accA[ar * 4 + ac] = fma2(dd, wA[ky * 3 + kx], accA[ar * 4 + ac]);
                            accB[ar * 4 + ac] = fma2(dd, wB[ky * 3 + kx], accB[ar * 4 + ac]);
                        }
                    }
                }
            }
        }
    }
}

// pool(2x2)+relu+store the 2x2 pooled outputs of a full 4x4 tile (one oc-pair)
__device__ __forceinline__ void pool_store_2oc(
    float* __restrict__ dst, const ull* __restrict__ acc,
    int pair, int plane, int rs, int py0, int px0)
{
    #pragma unroll
    for (int i = 0; i < 2; i++) {
        #pragma unroll
        for (int j = 0; j < 2; j++) {
            float l0, h0, l1, h1, l2, h2, l3, h3;
            unpack2(acc[(2 * i) * 4 + 2 * j],         l0, h0);
            unpack2(acc[(2 * i) * 4 + 2 * j + 1],     l1, h1);
            unpack2(acc[(2 * i + 1) * 4 + 2 * j],     l2, h2);
            unpack2(acc[(2 * i + 1) * 4 + 2 * j + 1], l3, h3);
            const float mlo = fmaxf(fmaxf(l0, l1), fmaxf(l2, l3));
            const float mhi = fmaxf(fmaxf(h0, h1), fmaxf(h2, h3));
            dst[(2 * pair)     * plane + (py0 + i) * rs + (px0 + j)] = fmaxf(mlo, 0.f);
            dst[(2 * pair + 1) * plane + (py0 + i) * rs + (px0 + j)] = fmaxf(mhi, 0.f);
        }
    }
}

// pool(2x2)+relu+store 1 pooled row x 2 pooled cols from a 2x4 half tile
__device__ __forceinline__ void pool_store_half(
    float* __restrict__ dst, const ull* __restrict__ acc,
    int pair, int plane, int rs, int pr, int pc0)
{
    #pragma unroll
    for (int j = 0; j < 2; j++) {
        float l0, h0, l1, h1, l2, h2, l3, h3;
        unpack2(acc[2 * j],         l0, h0);
        unpack2(acc[2 * j + 1],     l1, h1);
        unpack2(acc[4 + 2 * j],     l2, h2);
        unpack2(acc[4 + 2 * j + 1], l3, h3);
        const float mlo = fmaxf(fmaxf(l0, l1), fmaxf(l2, l3));
        const float mhi = fmaxf(fmaxf(h0, h1), fmaxf(h2, h3));
        dst[(2 * pair)     * plane + pr * rs + pc0 + j] = fmaxf(mlo, 0.f);
        dst[(2 * pair + 1) * plane + pr * rs + pc0 + j] = fmaxf(mhi, 0.f);
    }
}

// ---------------------------------------------------------------------------
// Fused kernel: one block per image.
// ---------------------------------------------------------------------------
__global__ __launch_bounds__(NTHREADS, 1) void qp_fused_kernel(
    const float* __restrict__ x,
    const float* __restrict__ w1g, const float* __restrict__ b1g,
    const float* __restrict__ w2g, const float* __restrict__ b2g,
    const float* __restrict__ fw,  const float* __restrict__ fb,
    float* __restrict__ out)
{
    extern __shared__ float smem[];
    float* sH1  = smem;                 // padded [32][26][28]
    float* sImg = smem + REG2_OFF;      // phase1 alias: padded image [3][54][56]
    float* sW2f = smem + REG2_OFF;      // later: conv2 weights ull2[16][32][9]
    float* sH2  = smem + SH2_OFF;       // [64][12][12]

    __shared__ __align__(16) float sW1f[864];   // conv1 weights ull2[8][3][9]
    __shared__ float2 sB1[16];
    __shared__ float2 sB2[32];
    __shared__ float  sRed[12][6];

    const int tid  = threadIdx.x;
    const int bimg = blockIdx.x;
    const float* xp = x + (size_t)bimg * X_COLS;

    // ---- stage image (padded rows) + conv1 weights (grouped ull2 taps) ----
    for (int i = tid; i < N_IMG; i += NTHREADS) {
        const int ic = i / (IMG_HW * IMG_HW);
        const int rm = i % (IMG_HW * IMG_HW);
        sImg[ic * IMG_PL + (rm / IMG_HW) * IMG_RS + (rm % IMG_HW)] = xp[i];
    }
    // w1 layout: l = oc*27 + ic*9 + tap  ->  [g=oc/4][ic][tap][pairsel][oc&1]
    for (int l = tid; l < 864; l += NTHREADS) {
        const int oc = l / 27, r = l % 27;
        const int g = oc >> 2, psel = (oc >> 1) & 1;
        sW1f[(((g * 3 + r / 9) * 9 + r % 9) * 2 + psel) * 2 + (oc & 1)] = w1g[l];
    }
    if (tid < 16) sB1[tid] = make_float2(b1g[2 * tid], b1g[2 * tid + 1]);
    if (tid < 32) sB2[tid] = make_float2(b2g[2 * tid], b2g[2 * tid + 1]);
    __syncthreads();

    // ---- phase 1: conv1 (3->32) + relu + pool ----
    // items: 8 groups (4 oc) x 169 full tiles = 1352
    {
        const ulonglong2* sW1 = reinterpret_cast<const ulonglong2*>(sW1f);
        const ull* sB1u = reinterpret_cast<const ull*>(sB1);
        for (int idx = tid; idx < 1352; idx += NTHREADS) {
            const int g = idx / 169, t = idx % 169;
            const int ty = t / 13, tx = t % 13;
            ull accA[16], accB[16];
            const ull bzA = sB1u[2 * g], bzB = sB1u[2 * g + 1];
            #pragma unroll
            for (int k = 0; k < 16; k++) { accA[k] = bzA; accB[k] = bzB; }
            #pragma unroll
            for (int ic = 0; ic < 3; ic++) {
                ull wA[9], wB[9];
                const ulonglong2* wp = sW1 + (g * 3 + ic) * 9;
                #pragma unroll
                for (int k = 0; k < 9; k++) {
                    const ulonglong2 wv = wp[k];
                    wA[k] = wv.x; wB[k] = wv.y;
                }
                conv_tile_4oc(sImg + ic * IMG_PL + (ty * 4) * IMG_RS + tx * 4,
                              IMG_RS, wA, wB, accA, accB);
            }
            pool_store_2oc(sH1, accA, 2 * g,     H1_PL, H1_RS, ty * 2, tx * 2);
            pool_store_2oc(sH1, accB, 2 * g + 1, H1_PL, H1_RS, ty * 2, tx * 2);
        }
    }
    __syncthreads();

    // ---- stage conv2 weights (grouped ull2 taps; overwrites image) ----
    // w2 layout: l = oc*288 + ic*9 + tap -> [g=oc/4][ic][tap][pairsel][oc&1]
    for (int l4 = tid * 4; l4 < 18432; l4 += NTHREADS * 4) {
        const float4 v = *reinterpret_cast<const float4*>(w2g + l4);
        const float e[4] = {v.x, v.y, v.z, v.w};
        #pragma unroll
        for (int k = 0; k < 4; k++) {
            const int l = l4 + k;
            const int oc = l / 288, r = l % 288;
            const int g = oc >> 2, psel = (oc >> 1) & 1;
            sW2f[(((g * 32 + r / 9) * 9 + r % 9) * 2 + psel) * 2 + (oc & 1)] = e[k];
        }
    }
    __syncthreads();

    // ---- phase 2: conv2 (32->64) + relu + pool ----
    // items: 16 groups x 12 pooled rows x 6 col-tiles = 1152 (exactly 3/thread)
    {
        const ulonglong2* sW2 = reinterpret_cast<const ulonglong2*>(sW2f);
        const ull* sB2u = reinterpret_cast<const ull*>(sB2);
        for (int idx = tid; idx < 1152; idx += NTHREADS) {
            const int g = idx / 72, rem = idx % 72;
            const int pr = rem / 6, ct = rem % 6;
            ull accA[8], accB[8];
            const ull bzA = sB2u[2 * g], bzB = sB2u[2 * g + 1];
            #pragma unroll
            for (int k = 0; k < 8; k++) { accA[k] = bzA; accB[k] = bzB; }
            // unroll 2: overlap next ic's LDS (weights+patch) with current fma2s
            #pragma unroll 2
            for (int ic = 0; ic < 32; ic++) {
                ull wA[9], wB[9];
                const ulonglong2* wp = sW2 + (g * 32 + ic) * 9;
                #pragma unroll
                for (int k = 0; k < 9; k++) {
                    const ulonglong2 wv = wp[k];
                    wA[k] = wv.x; wB[k] = wv.y;
                }
                conv_half_4oc(sH1 + ic * H1_PL + (2 * pr) * H1_RS + ct * 4,
                              H1_RS, wA, wB, accA, accB);
            }
            pool_store_half(sH2, accA, 2 * g,     P2 * P2, P2, pr, ct * 2);
            pool_store_half(sH2, accB, 2 * g + 1, P2 * P2, P2, pr, ct * 2);
        }
    }
    __syncthreads();

    // ---- phase 3: fcn (6 x 9219) + relu ----
    {
        float acc[6] = {0.f, 0.f, 0.f, 0.f, 0.f, 0.f};
        for (int j = tid; j < H2_PER; j += NTHREADS) {
            const float hv = sH2[j];
            #pragma unroll
            for (int o = 0; o < 6; o++)
                acc[o] = fmaf(hv, __ldg(fw + o * FCN_IN + j), acc[o]);
        }
        #pragma unroll
        for (int off = 16; off > 0; off >>= 1) {
            #pragma unroll
            for (int o = 0; o < 6; o++)
                acc[o] += __shfl_xor_sync(0xFFFFFFFFu, acc[o], off);
        }
        const int warp = tid >> 5, lane = tid & 31;
        if (lane == 0) {
            #pragma unroll
            for (int o = 0; o < 6; o++) sRed[warp][o] = acc[o];
        }
    }
    __syncthreads();

    if (tid == 0) {
        float yv[6];
        #pragma unroll
        for (int o = 0; o < 6; o++) {
            float s = 0.f;
            #pragma unroll
            for (int w = 0; w < 12; w++) s += sRed[w][o];
            #pragma unroll
            for (int k = 0; k < 3; k++)
                s = fmaf(xp[N_IMG + k], fw[o * FCN_IN + H2_PER + k], s);
            yv[o] = fmaxf(s + fb[o], 0.f);
        }

        // ---- double-precision 2x2 SVD clip + KKT (Schur) solve ----
        double A00 = yv[0], A01 = yv[1], A10 = yv[2], A11 = yv[3];
        const double b0 = yv[4], b1v = yv[5];

        const double E = 0.5 * (A00 + A11), F = 0.5 * (A00 - A11);
        const double G = 0.5 * (A10 + A01), H = 0.5 * (A10 - A01);
        const double Qh = sqrt(E * E + H * H);
        const double Rh = sqrt(F * F + G * G);
        const double s1 = Qh + Rh;
        const double s2 = fabs(Qh - Rh);

        if (s1 < 1e-300) {
            A00 = 0.01; A01 = 0.0; A10 = 0.0; A11 = 0.01;
        } else {
            const double s2c = fmax(s2, 0.1 * s1);
            if (s2c > s2) {
                const double p = A00 * A00 + A10 * A10;
                const double r = A01 * A01 + A11 * A11;
                const double q = A00 * A01 + A10 * A11;
                const double f = 0.5 * (p - r);
                const double disc = sqrt(f * f + q * q);
                double v1x, v1y;
                if (f >= 0.0) { v1x = disc + f; v1y = q; }
                else          { v1x = q;        v1y = disc - f; }
                double inv = 1.0 / sqrt(fmax(v1x * v1x + v1y * v1y, 1e-300));
                v1x *= inv; v1y *= inv;
                double v2x = -v1y, v2y = v1x;

                const double pB = A00 * A00 + A01 * A01;
                const double rB = A10 * A10 + A11 * A11;
                const double qB = A00 * A10 + A01 * A11;
                const double fB = 0.5 * (pB - rB);
                const double discB = sqrt(fB * fB + qB * qB);
                double u1x, u1y;
                if (fB >= 0.0) { u1x = discB + fB; u1y = qB; }
                else           { u1x = qB;         u1y = discB - fB; }
                inv = 1.0 / sqrt(fmax(u1x * u1x + u1y * u1y, 1e-300));
                u1x *= inv; u1y *= inv;
                double u2x = -u1y, u2y = u1x;

                const double tsgn = u2x * (A00 * v2x + A01 * v2y)
                                  + u2y * (A10 * v2x + A11 * v2y);
                if (tsgn < 0.0) { v2x = -v2x; v2y = -v2y; }

                const double d = s2c - s2;
                A00 += d * u2x * v2x; A01 += d * u2x * v2y;
                A10 += d * u2y * v2x; A11 += d * u2y * v2y;
            }
        }

        const double qi0 = 1.0, qi1 = 2.0;
        const double S00 = A00 * A00 * qi0 + A01 * A01 * qi1;
        const double S01 = A00 * A10 * qi0 + A01 * A11 * qi1;
        const double S11 = A10 * A10 * qi0 + A11 * A11 * qi1;
        const double r0 = A01 * 2000.0 - b0;
        const double r1 = A11 * 2000.0 - b1v;
        const double idet = 1.0 / (S00 * S11 - S01 * S01);
        const double l0 = (S11 * r0 - S01 * r1) * idet;
        const double l1 = (S00 * r1 - S01 * r0) * idet;
        out[bimg * 2 + 0] = (float)(-qi0 * (A00 * l0 + A10 * l1));
        out[bimg * 2 + 1] = (float)(2000.0 - qi1 * (A01 * l0 + A11 * l1));
    }
}

// ---------------------------------------------------------------------------
// Launcher (graph-capturable)
// ---------------------------------------------------------------------------
extern "C" void kernel_launch(void* const* d_in, const int* in_sizes, int n_in,
                              void* d_out, int out_size)
{
    const float* x  = (const float*)d_in[0];
    const float* w1 = (const float*)d_in[1];
    const float* b1 = (const float*)d_in[2];
    const float* w2 = (const float*)d_in[3];
    const float* b2 = (const float*)d_in[4];
    const float* fw = (const float*)d_in[5];
    const float* fb = (const float*)d_in[6];
    float* out = (float*)d_out;

    cudaFuncSetAttribute(qp_fused_kernel,
                         cudaFuncAttributeMaxDynamicSharedMemorySize, SMEM_BYTES);
    qp_fused_kernel<<<BATCH, NTHREADS, SMEM_BYTES>>>(x, w1, b1, w2, b2, fw, fb, out);
}